// round 6
// baseline (speedup 1.0000x reference)
#include <cuda_runtime.h>
#include <cuda_fp16.h>
#include <cstdint>

#define BATCH 32
#define VLEN  4096
#define HDIM  1024

// ---------------- device scratch ----------------
__device__ float g_qb[BATCH * HDIM];
__device__ float g_score[BATCH * VLEN];
__device__ __align__(16) __half g_wk[HDIM * HDIM];
__device__ float g_ctx_part[8 * BATCH * HDIM];   // v-split context partials

// ---------------- helpers ----------------
__device__ __forceinline__ uint32_t smem_u32(const void* p) {
    uint32_t a;
    asm("{ .reg .u64 t; cvta.to.shared.u64 t, %1; cvt.u32.u64 %0, t; }" : "=r"(a) : "l"(p));
    return a;
}
__device__ __forceinline__ void cp16(uint32_t saddr, const void* g) {
    asm volatile("cp.async.cg.shared.global [%0], [%1], 16;" :: "r"(saddr), "l"(g) : "memory");
}
#define CP_COMMIT() asm volatile("cp.async.commit_group;" ::: "memory")
#define CP_WAIT0()  asm volatile("cp.async.wait_group 0;" ::: "memory")

__device__ __forceinline__ void ldsm4(uint32_t* r, uint32_t addr) {
    asm volatile("ldmatrix.sync.aligned.m8n8.x4.shared.b16 {%0,%1,%2,%3}, [%4];"
                 : "=r"(r[0]), "=r"(r[1]), "=r"(r[2]), "=r"(r[3]) : "r"(addr));
}
__device__ __forceinline__ void mma_f16(float* d, const uint32_t* a, uint32_t b0, uint32_t b1) {
    asm volatile("mma.sync.aligned.m16n8k16.row.col.f32.f16.f16.f32 "
                 "{%0,%1,%2,%3}, {%4,%5,%6,%7}, {%8,%9}, {%0,%1,%2,%3};"
                 : "+f"(d[0]), "+f"(d[1]), "+f"(d[2]), "+f"(d[3])
                 : "r"(a[0]), "r"(a[1]), "r"(a[2]), "r"(a[3]), "r"(b0), "r"(b1));
}
__device__ __forceinline__ uint32_t pkh(float a, float b) {
    __half2 h = __floats2half2_rn(a, b);
    return *reinterpret_cast<uint32_t*>(&h);
}
// fast tanh: 1 - 2/(exp(2x)+1); MUFU-based, rel err ~1e-6
__device__ __forceinline__ float ftanh(float x) {
    float e = __expf(2.0f * x);
    return 1.0f - __fdividef(2.0f, e + 1.0f);
}

// ---------------- SMEM layout (bytes) ----------------
// K-chunk = 64 fp16 per row = 128 B, padded pitch 144 B.
// per buffer: [A 128*144 = 18432][B 256*144 = 36864] = 55296; 2 buffers.
#define PITCH    144
#define OFF_B    18432
#define BUFSZ    55296
#define SM_QB    (2 * BUFSZ)          // 110592, 1024 floats
#define SM_WS    (SM_QB + 4096)       // 114688
#define SM_RED   (SM_WS + 4096)       // 118784
#define SM_TOTAL (SM_RED + 2048)      // 120832

// ---------------------------------------------------------------------------
// Kernel 1: qb[b][o] = bias[o] + sum_h Wq[o][h] * query[b][h]
// ---------------------------------------------------------------------------
__global__ void qb_kernel(const float* __restrict__ query,
                          const float* __restrict__ Wq,
                          const float* __restrict__ bias) {
    int w    = (blockIdx.x * blockDim.x + threadIdx.x) >> 5;
    int lane = threadIdx.x & 31;
    int b = w / HDIM;
    int o = w % HDIM;
    const float* wrow = Wq + (size_t)o * HDIM;
    const float* qrow = query + (size_t)b * HDIM;
    float s = 0.0f;
#pragma unroll 8
    for (int h = lane; h < HDIM; h += 32) s += wrow[h] * qrow[h];
#pragma unroll
    for (int off = 16; off; off >>= 1) s += __shfl_xor_sync(0xffffffffu, s, off);
    if (lane == 0) g_qb[w] = s + bias[o];
}

// ---------------------------------------------------------------------------
// Kernel 1b: convert Wk to fp16
// ---------------------------------------------------------------------------
__global__ void wk_conv_kernel(const float* __restrict__ Wk) {
    int i = (blockIdx.x * 256 + threadIdx.x) * 4;
    float4 w = *reinterpret_cast<const float4*>(Wk + i);
    *reinterpret_cast<uint2*>(g_wk + i) = make_uint2(pkh(w.x, w.y), pkh(w.z, w.w));
}

// ---------------------------------------------------------------------------
// Kernel 2: score GEMM, single fp16 MMA per product (fp32 accumulate).
// Block: 128 v-rows x 256 o-cols per pass, 4 passes over o. K-chunk 64,
// double buffer; 64 chunks total (16 per pass).
// ---------------------------------------------------------------------------
__global__ void __launch_bounds__(256, 1)
score_kernel(const float* __restrict__ key, const float* __restrict__ Ws) {
    extern __shared__ __align__(16) char smem[];
    const uint32_t sb = smem_u32(smem);
    const int tid  = threadIdx.x;
    const int lane = tid & 31;
    const int wid  = tid >> 5;
    const int wy   = wid >> 2;   // 0..1 : M group (64 rows)
    const int wx   = wid & 3;    // 0..3 : N group (64 cols)
    const int b    = blockIdx.y;
    const int v0   = blockIdx.x * 128;

    float* qbs = reinterpret_cast<float*>(smem + SM_QB);
    float* wss = reinterpret_cast<float*>(smem + SM_WS);
#pragma unroll
    for (int i = 0; i < 4; i++) {
        qbs[tid + i * 256] = g_qb[b * HDIM + tid + i * 256];
        wss[tid + i * 256] = Ws[tid + i * 256];
    }

    const float* keyb = key + ((size_t)b * VLEN + v0) * HDIM;

    const int km = tid >> 1;            // key row 0..127
    const int kc = (tid & 1) * 32;      // key col base (fp32), 32 floats/thread
    const int wn = tid;                 // Wk row 0..255

    const uint32_t aoff  = (uint32_t)((lane & 15) * PITCH + (lane >> 4) * 16);
    const uint32_t Abase = sb + (uint32_t)(wy * 64 * PITCH) + aoff;
    const uint32_t Bbase = sb + OFF_B + (uint32_t)(wx * 64 * PITCH) + aoff;

    float d[4][8][4];
#pragma unroll
    for (int mt = 0; mt < 4; mt++)
#pragma unroll
        for (int j = 0; j < 8; j++)
#pragma unroll
            for (int q = 0; q < 4; q++) d[mt][j][q] = 0.0f;
    float part[8];
#pragma unroll
    for (int i = 0; i < 8; i++) part[i] = 0.0f;

    float4 kreg[8];

    // ---- prologue: chunk 0 into buffer 0 ----
    {
#pragma unroll
        for (int c = 0; c < 8; c++)
            cp16(sb + OFF_B + wn * PITCH + c * 16, g_wk + (size_t)wn * HDIM + c * 8);
        CP_COMMIT();
#pragma unroll
        for (int i = 0; i < 8; i++)
            kreg[i] = *reinterpret_cast<const float4*>(keyb + (size_t)km * HDIM + kc + i * 4);
        char* bufp = smem;
        const int boff = km * PITCH + kc * 2;
#pragma unroll
        for (int i = 0; i < 4; i++)
            *reinterpret_cast<uint4*>(bufp + boff + i * 16) =
                make_uint4(pkh(kreg[2*i].x, kreg[2*i].y), pkh(kreg[2*i].z, kreg[2*i].w),
                           pkh(kreg[2*i+1].x, kreg[2*i+1].y), pkh(kreg[2*i+1].z, kreg[2*i+1].w));
        CP_WAIT0();
        __syncthreads();
    }

    int cur = 0;
    for (int gc = 0; gc < 64; gc++) {
        const int nxt = cur ^ 1;
        // ---- issue loads for next chunk ----
        if (gc < 63) {
            const int n   = gc + 1;
            const int h0  = (n & 15) * 64;
            const int o0n = (n >> 4) * 256;
            const uint32_t bb = sb + (uint32_t)nxt * BUFSZ;
#pragma unroll
            for (int c = 0; c < 8; c++)
                cp16(bb + OFF_B + wn * PITCH + c * 16,
                     g_wk + (size_t)(o0n + wn) * HDIM + h0 + c * 8);
            CP_COMMIT();
#pragma unroll
            for (int i = 0; i < 8; i++)
                kreg[i] = *reinterpret_cast<const float4*>(keyb + (size_t)km * HDIM + h0 + kc + i * 4);
        }

        // ---- compute current chunk (K=64 -> 4 k16 steps) ----
        {
            const uint32_t abuf = Abase + (uint32_t)cur * BUFSZ;
            const uint32_t bbuf = Bbase + (uint32_t)cur * BUFSZ;
#pragma unroll
            for (int ks = 0; ks < 4; ks++) {
                uint32_t Bh[4][4];
#pragma unroll
                for (int jj = 0; jj < 4; jj++)
                    ldsm4(Bh[jj], bbuf + jj * (16 * PITCH) + ks * 32);
#pragma unroll
                for (int mt = 0; mt < 4; mt++) {
                    uint32_t Ah[4];
                    ldsm4(Ah, abuf + mt * (16 * PITCH) + ks * 32);
#pragma unroll
                    for (int jj = 0; jj < 4; jj++) {
#pragma unroll
                        for (int h = 0; h < 2; h++)
                            mma_f16(d[mt][jj * 2 + h], Ah, Bh[jj][h], Bh[jj][2 + h]);
                    }
                }
            }
        }

        // ---- store key for next chunk, wait Wk copies ----
        if (gc < 63) {
            char* bufp = smem + (size_t)nxt * BUFSZ;
            const int boff = km * PITCH + kc * 2;
#pragma unroll
            for (int i = 0; i < 4; i++)
                *reinterpret_cast<uint4*>(bufp + boff + i * 16) =
                    make_uint4(pkh(kreg[2*i].x, kreg[2*i].y), pkh(kreg[2*i].z, kreg[2*i].w),
                               pkh(kreg[2*i+1].x, kreg[2*i+1].y), pkh(kreg[2*i+1].z, kreg[2*i+1].w));
            CP_WAIT0();
        }
        __syncthreads();

        // ---- end of pass: tanh + Ws reduction, reset accumulators ----
        if ((gc & 15) == 15) {
            const int o0 = (gc >> 4) * 256;
            const int cb = o0 + wx * 64 + (lane & 3) * 2;
#pragma unroll
            for (int mt = 0; mt < 4; mt++) {
#pragma unroll
                for (int j = 0; j < 8; j++) {
                    const int o = cb + j * 8;
                    const float w0 = wss[o], w1 = wss[o + 1];
                    const float q0 = qbs[o], q1 = qbs[o + 1];
                    part[mt * 2 + 0] += w0 * ftanh(d[mt][j][0] + q0) + w1 * ftanh(d[mt][j][1] + q1);
                    part[mt * 2 + 1] += w0 * ftanh(d[mt][j][2] + q0) + w1 * ftanh(d[mt][j][3] + q1);
                    d[mt][j][0] = 0.0f; d[mt][j][1] = 0.0f;
                    d[mt][j][2] = 0.0f; d[mt][j][3] = 0.0f;
                }
            }
        }
        cur ^= 1;
    }

    // ---- cross-thread reduction ----
#pragma unroll
    for (int i = 0; i < 8; i++) {
        part[i] += __shfl_xor_sync(0xffffffffu, part[i], 1);
        part[i] += __shfl_xor_sync(0xffffffffu, part[i], 2);
    }
    float* red = reinterpret_cast<float*>(smem + SM_RED);
    if ((lane & 3) == 0) {
        const int r0 = wy * 64 + (lane >> 2);
#pragma unroll
        for (int mt = 0; mt < 4; mt++) {
            red[wx * 128 + r0 + mt * 16]     = part[mt * 2 + 0];
            red[wx * 128 + r0 + mt * 16 + 8] = part[mt * 2 + 1];
        }
    }
    __syncthreads();
    if (tid < 128) {
        const float s = red[tid] + red[128 + tid] + red[256 + tid] + red[384 + tid];
        g_score[b * VLEN + v0 + tid] = s;
    }
}

// ---------------------------------------------------------------------------
// Kernel 3: softmax over V=4096 per batch
// ---------------------------------------------------------------------------
__global__ void softmax_kernel(float* __restrict__ attn_out) {
    __shared__ float red[256];
    const int b = blockIdx.x;
    const int t = threadIdx.x;
    const float* s = g_score + b * VLEN;

    float local[16];
    float mx = -1e30f;
#pragma unroll
    for (int i = 0; i < 16; i++) {
        local[i] = s[t + i * 256];
        mx = fmaxf(mx, local[i]);
    }
    red[t] = mx;
    __syncthreads();
    for (int o = 128; o; o >>= 1) {
        if (t < o) red[t] = fmaxf(red[t], red[t + o]);
        __syncthreads();
    }
    mx = red[0];
    __syncthreads();

    float sum = 0.0f;
#pragma unroll
    for (int i = 0; i < 16; i++) {
        local[i] = expf(local[i] - mx);
        sum += local[i];
    }
    red[t] = sum;
    __syncthreads();
    for (int o = 128; o; o >>= 1) {
        if (t < o) red[t] += red[t + o];
        __syncthreads();
    }
    const float inv = 1.0f / red[0];
#pragma unroll
    for (int i = 0; i < 16; i++) attn_out[b * VLEN + t + i * 256] = local[i] * inv;
}

// ---------------------------------------------------------------------------
// Kernel 4a: context partials with v-split (512 blocks for full-chip MLP)
// ---------------------------------------------------------------------------
__global__ void context_part_kernel(const float* __restrict__ value,
                                    const float* __restrict__ attn) {
    __shared__ float a_s[512];
    const int hc = blockIdx.x, b = blockIdx.y, vs = blockIdx.z;
    const int v0 = vs * 512;
    const float* ap = attn + b * VLEN + v0;
    for (int i = threadIdx.x; i < 512; i += 128) a_s[i] = ap[i];
    __syncthreads();

    const int h = hc * 512 + threadIdx.x * 4;
    const float* vp = value + ((size_t)b * VLEN + v0) * HDIM + h;
    float ax = 0.f, ay = 0.f, az = 0.f, aw = 0.f;
    for (int v = 0; v < 512; v += 8) {
#pragma unroll
        for (int j = 0; j < 8; j++) {
            const float4 x = *reinterpret_cast<const float4*>(vp + (size_t)(v + j) * HDIM);
            const float a = a_s[v + j];
            ax += a * x.x; ay += a * x.y; az += a * x.z; aw += a * x.w;
        }
    }
    *reinterpret_cast<float4*>(g_ctx_part + ((size_t)vs * BATCH + b) * HDIM + h) =
        make_float4(ax, ay, az, aw);
}

// Kernel 4b: reduce 8 partials
__global__ void context_reduce_kernel(float* __restrict__ ctx) {
    const int i = blockIdx.x * 256 + threadIdx.x;
    float s = 0.0f;
#pragma unroll
    for (int vs = 0; vs < 8; vs++) s += g_ctx_part[vs * BATCH * HDIM + i];
    ctx[i] = s;
}

// ---------------------------------------------------------------------------
// Launch. Inputs: query, key, value, Wq, Wk, bias, Ws, bs.
// Output: context (32*1024) then attn (32*4096).
// ---------------------------------------------------------------------------
extern "C" void kernel_launch(void* const* d_in, const int* in_sizes, int n_in,
                              void* d_out, int out_size) {
    const float* query = (const float*)d_in[0];
    const float* key   = (const float*)d_in[1];
    const float* value = (const float*)d_in[2];
    const float* Wq    = (const float*)d_in[3];
    const float* Wk    = (const float*)d_in[4];
    const float* bias  = (const float*)d_in[5];
    const float* Ws    = (const float*)d_in[6];

    float* out  = (float*)d_out;
    float* ctx  = out;                    // (B, 1, H)
    float* attn = out + BATCH * HDIM;     // (B, V)

    cudaFuncSetAttribute(score_kernel, cudaFuncAttributeMaxDynamicSharedMemorySize, SM_TOTAL);

    qb_kernel<<<(BATCH * HDIM * 32) / 256, 256>>>(query, Wq, bias);
    wk_conv_kernel<<<(HDIM * HDIM) / (256 * 4), 256>>>(Wk);
    score_kernel<<<dim3(VLEN / 128, BATCH), 256, SM_TOTAL>>>(key, Ws);
    softmax_kernel<<<BATCH, 256>>>(attn);
    context_part_kernel<<<dim3(2, BATCH, 8), 128>>>(value, attn);
    context_reduce_kernel<<<(BATCH * HDIM) / 256, 256>>>(ctx);
}

// round 7
// speedup vs baseline: 1.0311x; 1.0311x over previous
#include <cuda_runtime.h>
#include <cuda_fp16.h>
#include <cstdint>

#define BATCH 32
#define VLEN  4096
#define HDIM  1024

// ---------------- device scratch ----------------
__device__ float g_qb[BATCH * HDIM];
__device__ float g_score[BATCH * VLEN];
__device__ __align__(16) __half g_wk[HDIM * HDIM];
__device__ __align__(16) __half g_key16[(size_t)BATCH * VLEN * HDIM];
__device__ float g_ctx_part[8 * BATCH * HDIM];   // v-split context partials

// ---------------- helpers ----------------
__device__ __forceinline__ uint32_t smem_u32(const void* p) {
    uint32_t a;
    asm("{ .reg .u64 t; cvta.to.shared.u64 t, %1; cvt.u32.u64 %0, t; }" : "=r"(a) : "l"(p));
    return a;
}
__device__ __forceinline__ void cp16(uint32_t saddr, const void* g) {
    asm volatile("cp.async.cg.shared.global [%0], [%1], 16;" :: "r"(saddr), "l"(g) : "memory");
}
#define CP_COMMIT() asm volatile("cp.async.commit_group;" ::: "memory")
#define CP_WAIT0()  asm volatile("cp.async.wait_group 0;" ::: "memory")

__device__ __forceinline__ void ldsm4(uint32_t* r, uint32_t addr) {
    asm volatile("ldmatrix.sync.aligned.m8n8.x4.shared.b16 {%0,%1,%2,%3}, [%4];"
                 : "=r"(r[0]), "=r"(r[1]), "=r"(r[2]), "=r"(r[3]) : "r"(addr));
}
__device__ __forceinline__ void mma_f16(float* d, const uint32_t* a, uint32_t b0, uint32_t b1) {
    asm volatile("mma.sync.aligned.m16n8k16.row.col.f32.f16.f16.f32 "
                 "{%0,%1,%2,%3}, {%4,%5,%6,%7}, {%8,%9}, {%0,%1,%2,%3};"
                 : "+f"(d[0]), "+f"(d[1]), "+f"(d[2]), "+f"(d[3])
                 : "r"(a[0]), "r"(a[1]), "r"(a[2]), "r"(a[3]), "r"(b0), "r"(b1));
}
__device__ __forceinline__ uint32_t pkh(float a, float b) {
    __half2 h = __floats2half2_rn(a, b);
    return *reinterpret_cast<uint32_t*>(&h);
}
// fast tanh: 1 - 2/(exp(2x)+1); MUFU-based, rel err ~1e-6
__device__ __forceinline__ float ftanh(float x) {
    float e = __expf(2.0f * x);
    return 1.0f - __fdividef(2.0f, e + 1.0f);
}

// ---------------- SMEM layout (bytes) ----------------
// K-chunk 32 fp16 = 64 B data per row, pitch 80 B.
// per buffer: [A 128*80 = 10240][B 256*80 = 20480] = 30720; 2 buffers
#define PITCH    80
#define OFF_B    10240
#define BUFSZ    30720
#define SM_QB    (2 * BUFSZ)          // 61440, 1024 floats
#define SM_WS    (SM_QB + 4096)
#define SM_RED   (SM_WS + 4096)
#define SM_TOTAL (SM_RED + 2048)      // 71680

// ---------------------------------------------------------------------------
// Kernel 1: qb[b][o] = bias[o] + sum_h Wq[o][h] * query[b][h]
// ---------------------------------------------------------------------------
__global__ void qb_kernel(const float* __restrict__ query,
                          const float* __restrict__ Wq,
                          const float* __restrict__ bias) {
    int w    = (blockIdx.x * blockDim.x + threadIdx.x) >> 5;
    int lane = threadIdx.x & 31;
    int b = w / HDIM;
    int o = w % HDIM;
    const float* wrow = Wq + (size_t)o * HDIM;
    const float* qrow = query + (size_t)b * HDIM;
    float s = 0.0f;
#pragma unroll 8
    for (int h = lane; h < HDIM; h += 32) s += wrow[h] * qrow[h];
#pragma unroll
    for (int off = 16; off; off >>= 1) s += __shfl_xor_sync(0xffffffffu, s, off);
    if (lane == 0) g_qb[w] = s + bias[o];
}

// ---------------------------------------------------------------------------
// Kernel 1b: convert Wk to fp16
// ---------------------------------------------------------------------------
__global__ void wk_conv_kernel(const float* __restrict__ Wk) {
    int i = (blockIdx.x * 256 + threadIdx.x) * 4;
    float4 w = *reinterpret_cast<const float4*>(Wk + i);
    *reinterpret_cast<uint2*>(g_wk + i) = make_uint2(pkh(w.x, w.y), pkh(w.z, w.w));
}

// ---------------------------------------------------------------------------
// Kernel 1c: convert key to fp16 (bandwidth-bound pre-pass, ~125us)
// ---------------------------------------------------------------------------
__global__ void key_conv_kernel(const float* __restrict__ key) {
    const size_t i = ((size_t)blockIdx.x * 256 + threadIdx.x) * 8;
    const float4 a = *reinterpret_cast<const float4*>(key + i);
    const float4 b = *reinterpret_cast<const float4*>(key + i + 4);
    *reinterpret_cast<uint4*>(g_key16 + i) =
        make_uint4(pkh(a.x, a.y), pkh(a.z, a.w), pkh(b.x, b.y), pkh(b.z, b.w));
}

// ---------------------------------------------------------------------------
// Kernel 2: score GEMM, single fp16 MMA per product (fp32 accumulate).
// Block: 128 v-rows x 256 o-cols per pass, 4 passes. K-chunk 32, double
// buffer; A and B tiles both pure cp.async (key pre-converted to fp16).
// ---------------------------------------------------------------------------
__global__ void __launch_bounds__(256, 1)
score_kernel(const float* __restrict__ Ws) {
    extern __shared__ __align__(16) char smem[];
    const uint32_t sb = smem_u32(smem);
    const int tid  = threadIdx.x;
    const int lane = tid & 31;
    const int wid  = tid >> 5;
    const int wy   = wid >> 2;   // 0..1 : M group (64 rows)
    const int wx   = wid & 3;    // 0..3 : N group (64 cols)
    const int b    = blockIdx.y;
    const int v0   = blockIdx.x * 128;

    float* qbs = reinterpret_cast<float*>(smem + SM_QB);
    float* wss = reinterpret_cast<float*>(smem + SM_WS);
#pragma unroll
    for (int i = 0; i < 4; i++) {
        qbs[tid + i * 256] = g_qb[b * HDIM + tid + i * 256];
        wss[tid + i * 256] = Ws[tid + i * 256];
    }

    const __half* keyb = g_key16 + ((size_t)b * VLEN + v0) * HDIM;

    // A-tile cp.async mapping: 512 x 16B transfers, 2 per thread
    const int arow = tid >> 1;           // 0..127
    const int aseg = (tid & 1) * 2;      // {0,2}; segs of 8 fp16
    const int wn   = tid;                // Wk row 0..255

    const uint32_t aoff  = (uint32_t)((lane & 15) * PITCH + (lane >> 4) * 16);
    const uint32_t Abase = sb + (uint32_t)(wy * 64 * PITCH) + aoff;
    const uint32_t Bbase = sb + OFF_B + (uint32_t)(wx * 64 * PITCH) + aoff;

    float d[4][8][4];
#pragma unroll
    for (int mt = 0; mt < 4; mt++)
#pragma unroll
        for (int j = 0; j < 8; j++)
#pragma unroll
            for (int q = 0; q < 4; q++) d[mt][j][q] = 0.0f;
    float part[8];
#pragma unroll
    for (int i = 0; i < 8; i++) part[i] = 0.0f;

    // ---- prologue: chunk 0 into buffer 0 ----
    {
        cp16(sb + arow * PITCH + aseg * 16,       keyb + (size_t)arow * HDIM + aseg * 8);
        cp16(sb + arow * PITCH + (aseg + 1) * 16, keyb + (size_t)arow * HDIM + (aseg + 1) * 8);
#pragma unroll
        for (int c = 0; c < 4; c++)
            cp16(sb + OFF_B + wn * PITCH + c * 16, g_wk + (size_t)wn * HDIM + c * 8);
        CP_COMMIT();
        CP_WAIT0();
        __syncthreads();
    }

    int cur = 0;
    for (int gc = 0; gc < 128; gc++) {
        const int nxt = cur ^ 1;
        // ---- issue cp.async loads for next chunk ----
        if (gc < 127) {
            const int n   = gc + 1;
            const int h0  = (n & 31) * 32;
            const int o0n = (n >> 5) * 256;
            const uint32_t bb = sb + (uint32_t)nxt * BUFSZ;
            cp16(bb + arow * PITCH + aseg * 16,
                 keyb + (size_t)arow * HDIM + h0 + aseg * 8);
            cp16(bb + arow * PITCH + (aseg + 1) * 16,
                 keyb + (size_t)arow * HDIM + h0 + (aseg + 1) * 8);
#pragma unroll
            for (int c = 0; c < 4; c++)
                cp16(bb + OFF_B + wn * PITCH + c * 16,
                     g_wk + (size_t)(o0n + wn) * HDIM + h0 + c * 8);
            CP_COMMIT();
        }

        // ---- compute current chunk ----
        {
            const uint32_t abuf = Abase + (uint32_t)cur * BUFSZ;
            const uint32_t bbuf = Bbase + (uint32_t)cur * BUFSZ;
#pragma unroll
            for (int ks = 0; ks < 2; ks++) {
                uint32_t Bh[4][4];
#pragma unroll
                for (int jj = 0; jj < 4; jj++)
                    ldsm4(Bh[jj], bbuf + jj * (16 * PITCH) + ks * 32);
#pragma unroll
                for (int mt = 0; mt < 4; mt++) {
                    uint32_t Ah[4];
                    ldsm4(Ah, abuf + mt * (16 * PITCH) + ks * 32);
#pragma unroll
                    for (int jj = 0; jj < 4; jj++) {
#pragma unroll
                        for (int h = 0; h < 2; h++)
                            mma_f16(d[mt][jj * 2 + h], Ah, Bh[jj][h], Bh[jj][2 + h]);
                    }
                }
            }
        }

        // ---- drain next-chunk copies, flip ----
        if (gc < 127) CP_WAIT0();
        __syncthreads();

        // ---- end of pass: tanh + Ws reduction, reset accumulators ----
        if ((gc & 31) == 31) {
            const int o0 = (gc >> 5) * 256;
            const int cb = o0 + wx * 64 + (lane & 3) * 2;
#pragma unroll
            for (int mt = 0; mt < 4; mt++) {
#pragma unroll
                for (int j = 0; j < 8; j++) {
                    const int o = cb + j * 8;
                    const float w0 = wss[o], w1 = wss[o + 1];
                    const float q0 = qbs[o], q1 = qbs[o + 1];
                    part[mt * 2 + 0] += w0 * ftanh(d[mt][j][0] + q0) + w1 * ftanh(d[mt][j][1] + q1);
                    part[mt * 2 + 1] += w0 * ftanh(d[mt][j][2] + q0) + w1 * ftanh(d[mt][j][3] + q1);
                    d[mt][j][0] = 0.0f; d[mt][j][1] = 0.0f;
                    d[mt][j][2] = 0.0f; d[mt][j][3] = 0.0f;
                }
            }
        }
        cur ^= 1;
    }

    // ---- cross-thread reduction ----
#pragma unroll
    for (int i = 0; i < 8; i++) {
        part[i] += __shfl_xor_sync(0xffffffffu, part[i], 1);
        part[i] += __shfl_xor_sync(0xffffffffu, part[i], 2);
    }
    float* red = reinterpret_cast<float*>(smem + SM_RED);
    if ((lane & 3) == 0) {
        const int r0 = wy * 64 + (lane >> 2);
#pragma unroll
        for (int mt = 0; mt < 4; mt++) {
            red[wx * 128 + r0 + mt * 16]     = part[mt * 2 + 0];
            red[wx * 128 + r0 + mt * 16 + 8] = part[mt * 2 + 1];
        }
    }
    __syncthreads();
    if (tid < 128) {
        const float s = red[tid] + red[128 + tid] + red[256 + tid] + red[384 + tid];
        g_score[b * VLEN + v0 + tid] = s;
    }
}

// ---------------------------------------------------------------------------
// Kernel 3: softmax over V=4096 per batch
// ---------------------------------------------------------------------------
__global__ void softmax_kernel(float* __restrict__ attn_out) {
    __shared__ float red[256];
    const int b = blockIdx.x;
    const int t = threadIdx.x;
    const float* s = g_score + b * VLEN;

    float local[16];
    float mx = -1e30f;
#pragma unroll
    for (int i = 0; i < 16; i++) {
        local[i] = s[t + i * 256];
        mx = fmaxf(mx, local[i]);
    }
    red[t] = mx;
    __syncthreads();
    for (int o = 128; o; o >>= 1) {
        if (t < o) red[t] = fmaxf(red[t], red[t + o]);
        __syncthreads();
    }
    mx = red[0];
    __syncthreads();

    float sum = 0.0f;
#pragma unroll
    for (int i = 0; i < 16; i++) {
        local[i] = expf(local[i] - mx);
        sum += local[i];
    }
    red[t] = sum;
    __syncthreads();
    for (int o = 128; o; o >>= 1) {
        if (t < o) red[t] += red[t + o];
        __syncthreads();
    }
    const float inv = 1.0f / red[0];
#pragma unroll
    for (int i = 0; i < 16; i++) attn_out[b * VLEN + t + i * 256] = local[i] * inv;
}

// ---------------------------------------------------------------------------
// Kernel 4a: context partials with v-split (512 blocks for full-chip MLP)
// ---------------------------------------------------------------------------
__global__ void context_part_kernel(const float* __restrict__ value,
                                    const float* __restrict__ attn) {
    __shared__ float a_s[512];
    const int hc = blockIdx.x, b = blockIdx.y, vs = blockIdx.z;
    const int v0 = vs * 512;
    const float* ap = attn + b * VLEN + v0;
    for (int i = threadIdx.x; i < 512; i += 128) a_s[i] = ap[i];
    __syncthreads();

    const int h = hc * 512 + threadIdx.x * 4;
    const float* vp = value + ((size_t)b * VLEN + v0) * HDIM + h;
    float ax = 0.f, ay = 0.f, az = 0.f, aw = 0.f;
    for (int v = 0; v < 512; v += 8) {
#pragma unroll
        for (int j = 0; j < 8; j++) {
            const float4 x = *reinterpret_cast<const float4*>(vp + (size_t)(v + j) * HDIM);
            const float a = a_s[v + j];
            ax += a * x.x; ay += a * x.y; az += a * x.z; aw += a * x.w;
        }
    }
    *reinterpret_cast<float4*>(g_ctx_part + ((size_t)vs * BATCH + b) * HDIM + h) =
        make_float4(ax, ay, az, aw);
}

// Kernel 4b: reduce 8 partials
__global__ void context_reduce_kernel(float* __restrict__ ctx) {
    const int i = blockIdx.x * 256 + threadIdx.x;
    float s = 0.0f;
#pragma unroll
    for (int vs = 0; vs < 8; vs++) s += g_ctx_part[vs * BATCH * HDIM + i];
    ctx[i] = s;
}

// ---------------------------------------------------------------------------
// Launch. Inputs: query, key, value, Wq, Wk, bias, Ws, bs.
// Output: context (32*1024) then attn (32*4096).
// ---------------------------------------------------------------------------
extern "C" void kernel_launch(void* const* d_in, const int* in_sizes, int n_in,
                              void* d_out, int out_size) {
    const float* query = (const float*)d_in[0];
    const float* key   = (const float*)d_in[1];
    const float* value = (const float*)d_in[2];
    const float* Wq    = (const float*)d_in[3];
    const float* Wk    = (const float*)d_in[4];
    const float* bias  = (const float*)d_in[5];
    const float* Ws    = (const float*)d_in[6];

    float* out  = (float*)d_out;
    float* ctx  = out;                    // (B, 1, H)
    float* attn = out + BATCH * HDIM;     // (B, V)

    cudaFuncSetAttribute(score_kernel, cudaFuncAttributeMaxDynamicSharedMemorySize, SM_TOTAL);

    qb_kernel<<<(BATCH * HDIM * 32) / 256, 256>>>(query, Wq, bias);
    wk_conv_kernel<<<(HDIM * HDIM) / (256 * 4), 256>>>(Wk);
    key_conv_kernel<<<(int)(((size_t)BATCH * VLEN * HDIM) / (256 * 8)), 256>>>(key);
    score_kernel<<<dim3(VLEN / 128, BATCH), 256, SM_TOTAL>>>(Ws);
    softmax_kernel<<<BATCH, 256>>>(attn);
    context_part_kernel<<<dim3(2, BATCH, 8), 128>>>(value, attn);
    context_reduce_kernel<<<(BATCH * HDIM) / 256, 256>>>(ctx);
}